// round 13
// baseline (speedup 1.0000x reference)
#include <cuda_runtime.h>
#include <cuda_fp16.h>
#include <cstdint>
#include <cstddef>

// Problem dims (fixed)
#define B_DIM  4096
#define H_DIM  1024
#define FOURH  4096
#define K_DIM  2048

// GEMM tiling
#define BM 128
#define BN 128
#define BK 64
#define NSTAGE 3
#define NIT (K_DIM / BK)               // 32
#define STAGE_U4 2048                  // 32KB per stage (A 16KB + B 16KB) in uint4
#define SMEM_BYTES (NSTAGE * 32768)    // 98304

// fp16 fragment-packed operands (device scratch).
// g_Ah: [mblk 256][k16 128][lane 32] uint4 = {a0,a1,a2,a3} of m16n8k16 A-frag
// g_Bh: [nblk 512][k32  64][lane 32] uint4 = {b0,b1 (k16#0), b0,b1 (k16#1)}
__device__ uint4 g_Ah[(size_t)256 * 128 * 32];
__device__ uint4 g_Bh[(size_t)512 * 64 * 32];
__device__ float g_bias[FOURH];   // permuted bias

// ---------------------------------------------------------------------------
__device__ __forceinline__ uint32_t pack_h2(float lo, float hi) {
    __half2 h = __floats2half2_rn(lo, hi);
    return *reinterpret_cast<uint32_t*>(&h);
}
__device__ __forceinline__ uint32_t smem_u32(const void* p) {
    return (uint32_t)__cvta_generic_to_shared(p);
}
__device__ __forceinline__ void cp_async16(uint32_t dst, const void* src) {
    asm volatile("cp.async.cg.shared.global [%0], [%1], 16;\n" :: "r"(dst), "l"(src));
}
__device__ __forceinline__ float sig_f(float x) {
    return __fdividef(1.0f, 1.0f + __expf(-x));
}
__device__ __forceinline__ float tanh_f(float x) {
    return 1.0f - __fdividef(2.0f, __expf(2.0f * x) + 1.0f);
}
__device__ __forceinline__ void mma_f16(float* c, const uint4& a,
                                        uint32_t b0, uint32_t b1) {
    asm volatile(
        "mma.sync.aligned.m16n8k16.row.col.f32.f16.f16.f32 "
        "{%0,%1,%2,%3}, {%4,%5,%6,%7}, {%8,%9}, {%0,%1,%2,%3};\n"
        : "+f"(c[0]), "+f"(c[1]), "+f"(c[2]), "+f"(c[3])
        : "r"(a.x), "r"(a.y), "r"(a.z), "r"(a.w), "r"(b0), "r"(b1));
}

// ---------------------------------------------------------------------------
// Prepass A: pack [x|h] (fp32) into fp16 m16n8k16 A-fragment order.
// One warp per (mblk, k16). 256*128 = 32768 warps.
// ---------------------------------------------------------------------------
__global__ __launch_bounds__(256)
void prep_A(const float* __restrict__ x, const float* __restrict__ h)
{
    int w = blockIdx.x * 8 + (threadIdx.x >> 5);
    int lane = threadIdx.x & 31;
    int g = lane >> 2, tig = lane & 3;
    int mblk = w >> 7, k16 = w & 127;
    int m0 = mblk * 16, k0 = k16 * 16;

    const float* src = (k0 < H_DIM) ? x : h;
    int c0 = k0 & (H_DIM - 1);
    const float* r_g  = src + (size_t)(m0 + g    ) * H_DIM + c0;
    const float* r_g8 = src + (size_t)(m0 + g + 8) * H_DIM + c0;
    float2 v0 = *(const float2*)(r_g  + 2 * tig);
    float2 v1 = *(const float2*)(r_g8 + 2 * tig);
    float2 v2 = *(const float2*)(r_g  + 2 * tig + 8);
    float2 v3 = *(const float2*)(r_g8 + 2 * tig + 8);

    uint4 out;
    out.x = pack_h2(v0.x, v0.y);
    out.y = pack_h2(v1.x, v1.y);
    out.z = pack_h2(v2.x, v2.y);
    out.w = pack_h2(v3.x, v3.y);
    g_Ah[(size_t)w * 32 + lane] = out;
}

// ---------------------------------------------------------------------------
// Prepass B: W=[w_i;w_h] transpose + gate-interleave permute + fp16 pack.
// Permutation (32-wide groups so a 64x32 warp tile holds all 4 gates):
//   p = ublk*32 + gate*8 + uo   (ublk = u>>3, uo = u&7, u = h-unit)
//   n = gate*1024 + ublk*8 + uo
// One warp per (nblk, k32). 512*64 = 32768 warps.
// ---------------------------------------------------------------------------
__global__ __launch_bounds__(256)
void prep_B(const float* __restrict__ wi, const float* __restrict__ wh)
{
    int w = blockIdx.x * 8 + (threadIdx.x >> 5);
    int lane = threadIdx.x & 31;
    int g = lane >> 2, tig = lane & 3;
    int nblk = w >> 6, k32 = w & 63;
    int p = nblk * 8 + g;
    int ublk = p >> 5, gate = (p >> 3) & 3, uo = p & 7;
    int n = gate * 1024 + ublk * 8 + uo;
    int k0 = k32 * 32;

    const float* src = (k0 < H_DIM) ? wi : wh;
    int r0 = k0 & (H_DIM - 1);

    uint4 out;
    #pragma unroll
    for (int f = 0; f < 2; f++) {
        int kb = r0 + f * 16;
        float e0 = src[(size_t)(kb + 2 * tig    ) * FOURH + n];
        float e1 = src[(size_t)(kb + 2 * tig + 1) * FOURH + n];
        float e2 = src[(size_t)(kb + 2 * tig + 8) * FOURH + n];
        float e3 = src[(size_t)(kb + 2 * tig + 9) * FOURH + n];
        uint32_t b0 = pack_h2(e0, e1);
        uint32_t b1 = pack_h2(e2, e3);
        if (f == 0) { out.x = b0; out.y = b1; }
        else        { out.z = b0; out.w = b1; }
    }
    g_Bh[(size_t)w * 32 + lane] = out;
}

__global__ __launch_bounds__(256)
void prep_bias(const float* __restrict__ bi, const float* __restrict__ bh)
{
    int p = blockIdx.x * 256 + threadIdx.x;
    if (p >= FOURH) return;
    int ublk = p >> 5, gate = (p >> 3) & 3, uo = p & 7;
    int n = gate * 1024 + ublk * 8 + uo;
    g_bias[p] = bi[n] + bh[n];
}

// ---------------------------------------------------------------------------
// Main GEMM (fp16 MMA, fp32 accum) + fused LSTM gates.
// 256 threads, 8 warps x (64x32 warp tile), BK=64, 3-stage cp.async,
// 2 CTAs/SM -> 4 warps/SMSP.
// ---------------------------------------------------------------------------
__global__ __launch_bounds__(256, 2)
void lstm_gemm_mma(const float* __restrict__ c_t, float* __restrict__ out)
{
    extern __shared__ uint4 smem[];
    const int tid  = threadIdx.x;
    const int wid  = tid >> 5;
    const int lane = tid & 31;
    const int g    = lane >> 2;
    const int tig  = lane & 3;
    const int bm   = blockIdx.y * BM;
    const int bn   = blockIdx.x * BN;
    const int mblk0 = bm >> 4;    // 8 mblks per CTA
    const int nblk0 = bn >> 3;    // 16 nblks per CTA

    float acc[4][4][4];           // [mt][gate/nt][e]
    #pragma unroll
    for (int mt = 0; mt < 4; mt++)
        #pragma unroll
        for (int nt = 0; nt < 4; nt++)
            #pragma unroll
            for (int e = 0; e < 4; e++)
                acc[mt][nt][e] = 0.0f;

    // Stage layout (uint4): A [mb 8][k16 4][lane 32] then B [nb 16][k32 2][lane 32]
    #define LOAD_STAGE(s, it)                                                  \
    do {                                                                       \
        uint4* dst = smem + (s) * STAGE_U4;                                    \
        const uint4* srcA = g_Ah + (size_t)mblk0 * 4096 + (size_t)(it) * 128;  \
        _Pragma("unroll")                                                      \
        for (int i = 0; i < 4; i++) {                                          \
            int q = tid + i * 256;                                             \
            int mb = q >> 7, rest = q & 127;                                   \
            cp_async16(smem_u32(dst + q), srcA + (size_t)mb * 4096 + rest);    \
        }                                                                      \
        const uint4* srcB = g_Bh + (size_t)nblk0 * 2048 + (size_t)(it) * 64;   \
        _Pragma("unroll")                                                      \
        for (int i = 0; i < 4; i++) {                                          \
            int q = tid + i * 256;                                             \
            int nb = q >> 6, rest = q & 63;                                    \
            cp_async16(smem_u32(dst + 1024 + q),                               \
                       srcB + (size_t)nb * 2048 + rest);                       \
        }                                                                      \
        asm volatile("cp.async.commit_group;\n" ::: "memory");                 \
    } while (0)

    LOAD_STAGE(0, 0);
    LOAD_STAGE(1, 1);

    const int wmb = (wid >> 2) * 4;   // warp mblk base (2 warp-rows)
    const int wnb = (wid & 3) * 4;    // warp nblk base (4 warp-cols)

    for (int it = 0; it < NIT; it++) {
        if (it < NIT - 1)
            asm volatile("cp.async.wait_group 1;\n" ::: "memory");
        else
            asm volatile("cp.async.wait_group 0;\n" ::: "memory");
        __syncthreads();
        if (it + 2 < NIT) LOAD_STAGE((it + 2) % NSTAGE, it + 2);

        const uint4* As = smem + (it % NSTAGE) * STAGE_U4 + wmb * 128 + lane;
        const uint4* Bs = smem + (it % NSTAGE) * STAGE_U4 + 1024 + wnb * 64 + lane;

        #pragma unroll
        for (int kp = 0; kp < 2; kp++) {          // two k32 halves of BK=64
            uint4 bv[4];
            #pragma unroll
            for (int nt = 0; nt < 4; nt++)
                bv[nt] = Bs[nt * 64 + kp * 32];
            #pragma unroll
            for (int kk = 0; kk < 2; kk++) {      // two k16 steps per k32
                uint4 av[4];
                #pragma unroll
                for (int mt = 0; mt < 4; mt++)
                    av[mt] = As[mt * 128 + (kp * 2 + kk) * 32];
                #pragma unroll
                for (int mt = 0; mt < 4; mt++)
                    #pragma unroll
                    for (int nt = 0; nt < 4; nt++) {
                        uint32_t b0 = kk ? bv[nt].z : bv[nt].x;
                        uint32_t b1 = kk ? bv[nt].w : bv[nt].y;
                        mma_f16(acc[mt][nt], av[mt], b0, b1);
                    }
            }
        }
    }
    #undef LOAD_STAGE

    // ---- fused LSTM gate epilogue ----
    // Warp N-window = 32 p's = one 32-group: gate nt, u = ublk*8 + tig*2 + e.
    const int wm    = (wid >> 2) * 64;
    const int wn    = (wid & 3) * 32;
    const int pbase = bn + wn;              // 32-aligned
    const int u0    = (pbase >> 5) * 8 + tig * 2;

    float2 b2[4];
    #pragma unroll
    for (int nt = 0; nt < 4; nt++)
        b2[nt] = *(const float2*)&g_bias[pbase + nt * 8 + tig * 2];

    #pragma unroll
    for (int mt = 0; mt < 4; mt++) {
        #pragma unroll
        for (int rs = 0; rs < 2; rs++) {
            const int row = bm + wm + mt * 16 + rs * 8 + g;
            float2 cv = *(const float2*)&c_t[(size_t)row * H_DIM + u0];
            float ce[2] = {cv.x, cv.y};
            float hn[2], cn[2];
            #pragma unroll
            for (int e = 0; e < 2; e++) {
                float zi = acc[mt][0][rs * 2 + e] + (e ? b2[0].y : b2[0].x);
                float zf = acc[mt][1][rs * 2 + e] + (e ? b2[1].y : b2[1].x);
                float zg = acc[mt][2][rs * 2 + e] + (e ? b2[2].y : b2[2].x);
                float zo = acc[mt][3][rs * 2 + e] + (e ? b2[3].y : b2[3].x);
                float ig = sig_f(zi);
                float fg = sig_f(zf);
                float gg = tanh_f(zg);
                float og = sig_f(zo);
                float cnew = fg * ce[e] + ig * gg;
                cn[e] = cnew;
                hn[e] = og * tanh_f(cnew);
            }
            *(float2*)&out[(size_t)row * H_DIM + u0] = make_float2(hn[0], hn[1]);
            *(float2*)&out[(size_t)B_DIM * H_DIM + (size_t)row * H_DIM + u0] =
                make_float2(cn[0], cn[1]);
        }
    }
}

// ---------------------------------------------------------------------------
// Launch. Inputs: input, h_t, c_t, w_i, w_h, b_i, b_h
// ---------------------------------------------------------------------------
extern "C" void kernel_launch(void* const* d_in, const int* in_sizes, int n_in,
                              void* d_out, int out_size)
{
    const float* x   = (const float*)d_in[0];
    const float* h_t = (const float*)d_in[1];
    const float* c_t = (const float*)d_in[2];
    const float* w_i = (const float*)d_in[3];
    const float* w_h = (const float*)d_in[4];
    const float* b_i = (const float*)d_in[5];
    const float* b_h = (const float*)d_in[6];
    float* out = (float*)d_out;

    cudaFuncSetAttribute(lstm_gemm_mma,
                         cudaFuncAttributeMaxDynamicSharedMemorySize, SMEM_BYTES);

    prep_A<<<4096, 256>>>(x, h_t);
    prep_B<<<4096, 256>>>(w_i, w_h);
    prep_bias<<<FOURH / 256, 256>>>(b_i, b_h);

    lstm_gemm_mma<<<dim3(FOURH / BN, B_DIM / BM), 256, SMEM_BYTES>>>(c_t, out);
}

// round 15
// speedup vs baseline: 1.0489x; 1.0489x over previous
#include <cuda_runtime.h>
#include <cuda_fp16.h>
#include <cstdint>
#include <cstddef>

// Problem dims (fixed)
#define B_DIM  4096
#define H_DIM  1024
#define FOURH  4096
#define K_DIM  2048

// GEMM tiling (R11 shape: 4 warps x 64x64)
#define BM 128
#define BN 128
#define BK 64
#define NSTAGE 3
#define NIT (K_DIM / BK)               // 32
#define STAGE_U4 2048                  // 32KB per stage (A 16KB + B 16KB) in uint4
#define SMEM_BYTES (NSTAGE * 32768)    // 98304

// fp16 fragment-packed operands (device scratch).
// g_Ah: [mblk 256][k16 128][lane 32] uint4 = {a0,a1,a2,a3} of m16n8k16 A-frag
// g_Bh: [nblk 512][k32  64][lane 32] uint4 = {b0,b1 (k16#0), b0,b1 (k16#1)}
__device__ uint4 g_Ah[(size_t)256 * 128 * 32];
__device__ uint4 g_Bh[(size_t)512 * 64 * 32];
__device__ float g_bias[FOURH];   // permuted bias

// ---------------------------------------------------------------------------
__device__ __forceinline__ uint32_t pack_h2(float lo, float hi) {
    __half2 h = __floats2half2_rn(lo, hi);
    return *reinterpret_cast<uint32_t*>(&h);
}
__device__ __forceinline__ uint32_t smem_u32(const void* p) {
    return (uint32_t)__cvta_generic_to_shared(p);
}
__device__ __forceinline__ void cp_async16(uint32_t dst, const void* src) {
    asm volatile("cp.async.cg.shared.global [%0], [%1], 16;\n" :: "r"(dst), "l"(src));
}
__device__ __forceinline__ float sig_f(float x) {
    return __fdividef(1.0f, 1.0f + __expf(-x));
}
__device__ __forceinline__ float tanh_f(float x) {
    return 1.0f - __fdividef(2.0f, __expf(2.0f * x) + 1.0f);
}
__device__ __forceinline__ void mma_f16(float* c, const uint4& a,
                                        uint32_t b0, uint32_t b1) {
    asm volatile(
        "mma.sync.aligned.m16n8k16.row.col.f32.f16.f16.f32 "
        "{%0,%1,%2,%3}, {%4,%5,%6,%7}, {%8,%9}, {%0,%1,%2,%3};\n"
        : "+f"(c[0]), "+f"(c[1]), "+f"(c[2]), "+f"(c[3])
        : "r"(a.x), "r"(a.y), "r"(a.z), "r"(a.w), "r"(b0), "r"(b1));
}

// ---------------------------------------------------------------------------
// Fused prepass: blocks [0,4096) pack A, [4096,8192) pack B, [8192,8208) bias.
// A: one warp per (mblk, k16); fragment order {a0,a1,a2,a3}.
// B: one warp per (nblk, k32); gate-interleave p = ublk*64 + gate*16 + uo.
// ---------------------------------------------------------------------------
__global__ __launch_bounds__(256)
void prep_all(const float* __restrict__ x, const float* __restrict__ h,
              const float* __restrict__ wi, const float* __restrict__ wh,
              const float* __restrict__ bi, const float* __restrict__ bh)
{
    int blk = blockIdx.x;
    int lane = threadIdx.x & 31;
    int g = lane >> 2, tig = lane & 3;

    if (blk < 4096) {
        // ---- pack A ----
        int w = blk * 8 + (threadIdx.x >> 5);
        int mblk = w >> 7, k16 = w & 127;
        int m0 = mblk * 16, k0 = k16 * 16;
        const float* src = (k0 < H_DIM) ? x : h;
        int c0 = k0 & (H_DIM - 1);
        const float* r_g  = src + (size_t)(m0 + g    ) * H_DIM + c0;
        const float* r_g8 = src + (size_t)(m0 + g + 8) * H_DIM + c0;
        float2 v0 = *(const float2*)(r_g  + 2 * tig);
        float2 v1 = *(const float2*)(r_g8 + 2 * tig);
        float2 v2 = *(const float2*)(r_g  + 2 * tig + 8);
        float2 v3 = *(const float2*)(r_g8 + 2 * tig + 8);
        uint4 o;
        o.x = pack_h2(v0.x, v0.y);
        o.y = pack_h2(v1.x, v1.y);
        o.z = pack_h2(v2.x, v2.y);
        o.w = pack_h2(v3.x, v3.y);
        g_Ah[(size_t)w * 32 + lane] = o;
    } else if (blk < 8192) {
        // ---- pack B (transpose + gate-interleave) ----
        int w = (blk - 4096) * 8 + (threadIdx.x >> 5);
        int nblk = w >> 6, k32 = w & 63;
        int p = nblk * 8 + g;
        int ublk = p >> 6, gate = (p >> 4) & 3, uo = p & 15;
        int n = gate * 1024 + ublk * 16 + uo;
        int k0 = k32 * 32;
        const float* src = (k0 < H_DIM) ? wi : wh;
        int r0 = k0 & (H_DIM - 1);
        uint4 o;
        #pragma unroll
        for (int f = 0; f < 2; f++) {
            int kb = r0 + f * 16;
            float e0 = src[(size_t)(kb + 2 * tig    ) * FOURH + n];
            float e1 = src[(size_t)(kb + 2 * tig + 1) * FOURH + n];
            float e2 = src[(size_t)(kb + 2 * tig + 8) * FOURH + n];
            float e3 = src[(size_t)(kb + 2 * tig + 9) * FOURH + n];
            uint32_t b0 = pack_h2(e0, e1);
            uint32_t b1 = pack_h2(e2, e3);
            if (f == 0) { o.x = b0; o.y = b1; }
            else        { o.z = b0; o.w = b1; }
        }
        g_Bh[(size_t)w * 32 + lane] = o;
    } else {
        // ---- bias ----
        int p = (blk - 8192) * 256 + threadIdx.x;
        if (p < FOURH) {
            int ublk = p >> 6, gate = (p >> 4) & 3, uo = p & 15;
            int n = gate * 1024 + ublk * 16 + uo;
            g_bias[p] = bi[n] + bh[n];
        }
    }
}

// ---------------------------------------------------------------------------
// Main GEMM (fp16 MMA, fp32 accum) + fused LSTM gates.
// 128 threads, 4 warps x (64x64), BK=64, 3-stage cp.async pipeline,
// software-pipelined fragment loads (bv up-front, av double-buffered).
// ---------------------------------------------------------------------------
__global__ __launch_bounds__(128, 2)
void lstm_gemm_mma(const float* __restrict__ c_t, float* __restrict__ out)
{
    extern __shared__ uint4 smem[];
    const int tid  = threadIdx.x;
    const int wid  = tid >> 5;
    const int lane = tid & 31;
    const int g    = lane >> 2;
    const int tig  = lane & 3;
    const int bm   = blockIdx.y * BM;
    const int bn   = blockIdx.x * BN;
    const int mblk0 = bm >> 4;    // 8 mblks per CTA
    const int nblk0 = bn >> 3;    // 16 nblks per CTA

    float acc[4][8][4];
    #pragma unroll
    for (int mt = 0; mt < 4; mt++)
        #pragma unroll
        for (int nt = 0; nt < 8; nt++)
            #pragma unroll
            for (int e = 0; e < 4; e++)
                acc[mt][nt][e] = 0.0f;

    // Stage layout (uint4): A [mb 8][k16 4][lane 32] then B [nb 16][k32 2][lane 32]
    #define LOAD_STAGE(s, it)                                                  \
    do {                                                                       \
        uint4* dst = smem + (s) * STAGE_U4;                                    \
        const uint4* srcA = g_Ah + (size_t)mblk0 * 4096 + (size_t)(it) * 128;  \
        _Pragma("unroll")                                                      \
        for (int i = 0; i < 8; i++) {                                          \
            int q = tid + i * 128;                                             \
            int mb = q >> 7, rest = q & 127;                                   \
            cp_async16(smem_u32(dst + q), srcA + (size_t)mb * 4096 + rest);    \
        }                                                                      \
        const uint4* srcB = g_Bh + (size_t)nblk0 * 2048 + (size_t)(it) * 64;   \
        _Pragma("unroll")                                                      \
        for (int i = 0; i < 8; i++) {                                          \
            int q = tid + i * 128;                                             \
            int nb = q >> 6, rest = q & 63;                                    \
            cp_async16(smem_u32(dst + 1024 + q),                               \
                       srcB + (size_t)nb * 2048 + rest);                       \
        }                                                                      \
        asm volatile("cp.async.commit_group;\n" ::: "memory");                 \
    } while (0)

    LOAD_STAGE(0, 0);
    LOAD_STAGE(1, 1);

    const int wmb = (wid >> 1) * 4;   // warp mblk base
    const int wnb = (wid & 1) * 8;    // warp nblk base

    for (int it = 0; it < NIT; it++) {
        if (it < NIT - 1)
            asm volatile("cp.async.wait_group 1;\n" ::: "memory");
        else
            asm volatile("cp.async.wait_group 0;\n" ::: "memory");
        __syncthreads();

        const uint4* As = smem + (it % NSTAGE) * STAGE_U4 + wmb * 128 + lane;
        const uint4* Bs = smem + (it % NSTAGE) * STAGE_U4 + 1024 + wnb * 64 + lane;

        // Preload ALL B fragments for this iter (16 LDS.128) + first A step.
        uint4 bv[16];
        #pragma unroll
        for (int kp = 0; kp < 2; kp++)
            #pragma unroll
            for (int nt = 0; nt < 8; nt++)
                bv[kp * 8 + nt] = Bs[nt * 64 + kp * 32];

        uint4 av[2][4];
        #pragma unroll
        for (int mt = 0; mt < 4; mt++)
            av[0][mt] = As[mt * 128];

        // Issue next-stage prefetch AFTER fragment loads so LDS goes first.
        if (it + 2 < NIT) LOAD_STAGE((it + 2) % NSTAGE, it + 2);

        // 4 k16 steps; prefetch step ks+1's A frags during step ks's MMAs.
        #pragma unroll
        for (int ks = 0; ks < 4; ks++) {
            const int cb = ks & 1;
            if (ks < 3) {
                #pragma unroll
                for (int mt = 0; mt < 4; mt++)
                    av[cb ^ 1][mt] = As[mt * 128 + (ks + 1) * 32];
            }
            #pragma unroll
            for (int mt = 0; mt < 4; mt++)
                #pragma unroll
                for (int nt = 0; nt < 8; nt++) {
                    const uint4& b = bv[(ks >> 1) * 8 + nt];
                    uint32_t b0 = (ks & 1) ? b.z : b.x;
                    uint32_t b1 = (ks & 1) ? b.w : b.y;
                    mma_f16(acc[mt][nt], av[cb][mt], b0, b1);
                }
        }
    }
    #undef LOAD_STAGE

    // ---- fused LSTM gate epilogue (R11 mapping: 64-wide permute groups) ----
    const int wm   = (wid >> 1) * 64;
    const int wn   = (wid & 1) * 64;
    const int ublk = (bn + wn) >> 6;
    const int ucol = ublk * 16 + tig * 2;

    float2 bias2[8];
    #pragma unroll
    for (int nt = 0; nt < 8; nt++)
        bias2[nt] = *(const float2*)&g_bias[bn + wn + nt * 8 + tig * 2];

    #pragma unroll
    for (int mt = 0; mt < 4; mt++) {
        #pragma unroll
        for (int rs = 0; rs < 2; rs++) {
            const int row = bm + wm + mt * 16 + rs * 8 + g;
            #pragma unroll
            for (int hi = 0; hi < 2; hi++) {
                const int u = ucol + hi * 8;
                float2 cv = *(const float2*)&c_t[(size_t)row * H_DIM + u];
                float ce[2] = {cv.x, cv.y};
                float hn[2], cn[2];
                #pragma unroll
                for (int e = 0; e < 2; e++) {
                    float bi_i = e ? bias2[0 + hi].y : bias2[0 + hi].x;
                    float bi_f = e ? bias2[2 + hi].y : bias2[2 + hi].x;
                    float bi_g = e ? bias2[4 + hi].y : bias2[4 + hi].x;
                    float bi_o = e ? bias2[6 + hi].y : bias2[6 + hi].x;
                    float zi = acc[mt][0 + hi][rs * 2 + e] + bi_i;
                    float zf = acc[mt][2 + hi][rs * 2 + e] + bi_f;
                    float zg = acc[mt][4 + hi][rs * 2 + e] + bi_g;
                    float zo = acc[mt][6 + hi][rs * 2 + e] + bi_o;
                    float ig = sig_f(zi);
                    float fg = sig_f(zf);
                    float gg = tanh_f(zg);
                    float og = sig_f(zo);
                    float cnew = fg * ce[e] + ig * gg;
                    cn[e] = cnew;
                    hn[e] = og * tanh_f(cnew);
                }
                *(float2*)&out[(size_t)row * H_DIM + u] = make_float2(hn[0], hn[1]);
                *(float2*)&out[(size_t)B_DIM * H_DIM + (size_t)row * H_DIM + u] =
                    make_float2(cn[0], cn[1]);
            }
        }
    }
}

// ---------------------------------------------------------------------------
// Launch. Inputs: input, h_t, c_t, w_i, w_h, b_i, b_h
// ---------------------------------------------------------------------------
extern "C" void kernel_launch(void* const* d_in, const int* in_sizes, int n_in,
                              void* d_out, int out_size)
{
    const float* x   = (const float*)d_in[0];
    const float* h_t = (const float*)d_in[1];
    const float* c_t = (const float*)d_in[2];
    const float* w_i = (const float*)d_in[3];
    const float* w_h = (const float*)d_in[4];
    const float* b_i = (const float*)d_in[5];
    const float* b_h = (const float*)d_in[6];
    float* out = (float*)d_out;

    cudaFuncSetAttribute(lstm_gemm_mma,
                         cudaFuncAttributeMaxDynamicSharedMemorySize, SMEM_BYTES);

    prep_all<<<8208, 256>>>(x, h_t, w_i, w_h, b_i, b_h);

    lstm_gemm_mma<<<dim3(FOURH / BN, B_DIM / BM), 128, SMEM_BYTES>>>(c_t, out);
}

// round 16
// speedup vs baseline: 1.1923x; 1.1367x over previous
#include <cuda_runtime.h>
#include <cuda_fp16.h>
#include <cstdint>
#include <cstddef>

// Problem dims (fixed)
#define B_DIM  4096
#define H_DIM  1024
#define FOURH  4096
#define K_DIM  2048

// GEMM tiling: 4 warps x (64x64), BK=64
#define BM 128
#define BN 128
#define BK 64
#define NSTAGE 3
#define NIT (K_DIM / BK)               // 32
#define STAGE_U4 2048                  // 32KB per stage (A 16KB + B 16KB)
#define SMEM_BYTES (1024 + NSTAGE * 32768)   // 99328

// fp16 fragment-packed operands, stage-contiguous layout:
// g_A2: [mtile 32][it 32][mb 8][k16 4][lane 32] uint4  (16KB per (mtile,it))
// g_B2: [ntile 32][it 32][nb 16][k32 2][lane 32] uint4 (16KB per (ntile,it))
__device__ uint4 g_A2[(size_t)32 * 32 * 1024];
__device__ uint4 g_B2[(size_t)32 * 32 * 1024];
__device__ float g_bias[FOURH];   // permuted bias

// ---------------------------------------------------------------------------
__device__ __forceinline__ uint32_t pack_h2(float lo, float hi) {
    __half2 h = __floats2half2_rn(lo, hi);
    return *reinterpret_cast<uint32_t*>(&h);
}
__device__ __forceinline__ uint32_t smem_u32(const void* p) {
    return (uint32_t)__cvta_generic_to_shared(p);
}
__device__ __forceinline__ float sig_f(float x) {
    return __fdividef(1.0f, 1.0f + __expf(-x));
}
__device__ __forceinline__ float tanh_f(float x) {
    return 1.0f - __fdividef(2.0f, __expf(2.0f * x) + 1.0f);
}
__device__ __forceinline__ void mma_f16(float* c, const uint4& a,
                                        uint32_t b0, uint32_t b1) {
    asm volatile(
        "mma.sync.aligned.m16n8k16.row.col.f32.f16.f16.f32 "
        "{%0,%1,%2,%3}, {%4,%5,%6,%7}, {%8,%9}, {%0,%1,%2,%3};\n"
        : "+f"(c[0]), "+f"(c[1]), "+f"(c[2]), "+f"(c[3])
        : "r"(a.x), "r"(a.y), "r"(a.z), "r"(a.w), "r"(b0), "r"(b1));
}

#define MBAR_INIT(addr, cnt) \
    asm volatile("mbarrier.init.shared.b64 [%0], %1;" :: "r"(addr), "r"(cnt) : "memory")
#define MBAR_ARRIVE(addr) \
    asm volatile("mbarrier.arrive.shared.b64 _, [%0];" :: "r"(addr) : "memory")
#define MBAR_EXPECT_TX(addr, bytes) \
    asm volatile("mbarrier.arrive.expect_tx.shared.b64 _, [%0], %1;" \
                 :: "r"(addr), "r"(bytes) : "memory")
#define MBAR_WAIT(addr, ph) do {                                              \
    uint32_t _m = (addr); uint32_t _p = (ph); uint32_t _done;                 \
    asm volatile("{\n\t.reg .pred p;\n\t"                                     \
        "mbarrier.try_wait.parity.acquire.cta.shared::cta.b64 p, [%1], %2;\n\t" \
        "selp.b32 %0, 1, 0, p;\n\t}"                                          \
        : "=r"(_done) : "r"(_m), "r"(_p) : "memory");                         \
    if (!_done) {                                                             \
        asm volatile("{\n\t.reg .pred P1;\n\t"                                \
            "W_%=:\n\t"                                                       \
            "mbarrier.try_wait.parity.acquire.cta.shared::cta.b64 P1, [%0], %1, 0x989680;\n\t" \
            "@P1 bra.uni D_%=;\n\t"                                           \
            "bra.uni W_%=;\n\t"                                               \
            "D_%=:\n\t}"                                                      \
            :: "r"(_m), "r"(_p) : "memory");                                  \
    }                                                                         \
} while (0)

__device__ __forceinline__ void bulk_g2s(uint32_t smem_dst, const void* gsrc,
                                         uint32_t bytes, uint32_t mbar) {
    asm volatile(
        "cp.async.bulk.shared::cluster.global.mbarrier::complete_tx::bytes "
        "[%0], [%1], %2, [%3];"
        :: "r"(smem_dst), "l"(gsrc), "r"(bytes), "r"(mbar) : "memory");
}

// ---------------------------------------------------------------------------
// Fused prepass: blocks [0,4096) pack A, [4096,8192) pack B, [8192,8208) bias.
// A: one warp per (mblk, k16); B: one warp per (nblk, k32) with gate
// interleave p = ublk*64 + gate*16 + uo. Stage-contiguous destinations.
// ---------------------------------------------------------------------------
__global__ __launch_bounds__(256)
void prep_all(const float* __restrict__ x, const float* __restrict__ h,
              const float* __restrict__ wi, const float* __restrict__ wh,
              const float* __restrict__ bi, const float* __restrict__ bh)
{
    int blk = blockIdx.x;
    int lane = threadIdx.x & 31;
    int g = lane >> 2, tig = lane & 3;

    if (blk < 4096) {
        int w = blk * 8 + (threadIdx.x >> 5);
        int mblk = w >> 7, k16 = w & 127;
        int m0 = mblk * 16, k0 = k16 * 16;
        const float* src = (k0 < H_DIM) ? x : h;
        int c0 = k0 & (H_DIM - 1);
        const float* r_g  = src + (size_t)(m0 + g    ) * H_DIM + c0;
        const float* r_g8 = src + (size_t)(m0 + g + 8) * H_DIM + c0;
        float2 v0 = *(const float2*)(r_g  + 2 * tig);
        float2 v1 = *(const float2*)(r_g8 + 2 * tig);
        float2 v2 = *(const float2*)(r_g  + 2 * tig + 8);
        float2 v3 = *(const float2*)(r_g8 + 2 * tig + 8);
        uint4 o;
        o.x = pack_h2(v0.x, v0.y);
        o.y = pack_h2(v1.x, v1.y);
        o.z = pack_h2(v2.x, v2.y);
        o.w = pack_h2(v3.x, v3.y);
        int mtile = mblk >> 3, mb = mblk & 7, it = k16 >> 2, ki = k16 & 3;
        size_t idx = (((size_t)(mtile * 32 + it) * 8 + mb) * 4 + ki);
        g_A2[idx * 32 + lane] = o;
    } else if (blk < 8192) {
        int w = (blk - 4096) * 8 + (threadIdx.x >> 5);
        int nblk = w >> 6, k32 = w & 63;
        int p = nblk * 8 + g;
        int ublk = p >> 6, gate = (p >> 4) & 3, uo = p & 15;
        int n = gate * 1024 + ublk * 16 + uo;
        int k0 = k32 * 32;
        const float* src = (k0 < H_DIM) ? wi : wh;
        int r0 = k0 & (H_DIM - 1);
        uint4 o;
        #pragma unroll
        for (int f = 0; f < 2; f++) {
            int kb = r0 + f * 16;
            float e0 = src[(size_t)(kb + 2 * tig    ) * FOURH + n];
            float e1 = src[(size_t)(kb + 2 * tig + 1) * FOURH + n];
            float e2 = src[(size_t)(kb + 2 * tig + 8) * FOURH + n];
            float e3 = src[(size_t)(kb + 2 * tig + 9) * FOURH + n];
            uint32_t b0 = pack_h2(e0, e1);
            uint32_t b1 = pack_h2(e2, e3);
            if (f == 0) { o.x = b0; o.y = b1; }
            else        { o.z = b0; o.w = b1; }
        }
        int ntile = nblk >> 4, nb = nblk & 15, it = k32 >> 1, ki = k32 & 1;
        size_t idx = (((size_t)(ntile * 32 + it) * 16 + nb) * 2 + ki);
        g_B2[idx * 32 + lane] = o;
    } else {
        int p = (blk - 8192) * 256 + threadIdx.x;
        if (p < FOURH) {
            int ublk = p >> 6, gate = (p >> 4) & 3, uo = p & 15;
            int n = gate * 1024 + ublk * 16 + uo;
            g_bias[p] = bi[n] + bh[n];
        }
    }
}

// ---------------------------------------------------------------------------
// Main GEMM (fp16 MMA, fp32 accum) + fused LSTM gates.
// 128 threads, TMA-bulk stage loads (single producer thread), mbarrier ring,
// no per-iteration __syncthreads.
// ---------------------------------------------------------------------------
__global__ __launch_bounds__(128, 2)
void lstm_gemm_mma(const float* __restrict__ c_t, float* __restrict__ out)
{
    extern __shared__ uint4 smem[];
    const uint32_t sb = smem_u32(smem);
    const int tid  = threadIdx.x;
    const int wid  = tid >> 5;
    const int lane = tid & 31;
    const int g    = lane >> 2;
    const int tig  = lane & 3;
    const int mtile = blockIdx.y;
    const int ntile = blockIdx.x;
    const int bm   = mtile * BM;
    const int bn   = ntile * BN;

    // Barriers in first 1024B of dynamic smem; stages follow.
    const uint32_t FULL0  = sb;        // 3 x 8B
    const uint32_t EMPTY0 = sb + 32;   // 3 x 8B
    uint4* stage_base = smem + 64;     // 64 uint4 = 1024B

    if (tid == 0) {
        #pragma unroll
        for (int s = 0; s < NSTAGE; s++) {
            MBAR_INIT(FULL0  + 8 * s, 1);   // producer expect_tx
            MBAR_INIT(EMPTY0 + 8 * s, 4);   // 4 warps arrive
        }
    }
    __syncthreads();

    const uint4* srcA = g_A2 + (size_t)mtile * 32 * 1024;
    const uint4* srcB = g_B2 + (size_t)ntile * 32 * 1024;

    // Prologue: issue stages 0,1
    if (tid == 0) {
        #pragma unroll
        for (int j = 0; j < 2; j++) {
            uint32_t st = sb + 1024 + j * 32768;
            MBAR_EXPECT_TX(FULL0 + 8 * j, 32768u);
            bulk_g2s(st,         srcA + (size_t)j * 1024, 16384u, FULL0 + 8 * j);
            bulk_g2s(st + 16384, srcB + (size_t)j * 1024, 16384u, FULL0 + 8 * j);
        }
    }

    float acc[4][8][4];
    #pragma unroll
    for (int mt = 0; mt < 4; mt++)
        #pragma unroll
        for (int nt = 0; nt < 8; nt++)
            #pragma unroll
            for (int e = 0; e < 4; e++)
                acc[mt][nt][e] = 0.0f;

    const int wmb = (wid >> 1) * 4;   // warp mblk base
    const int wnb = (wid & 1) * 8;    // warp nblk base

    for (int it = 0; it < NIT; it++) {
        const int s = it % NSTAGE;

        // Producer: prefetch stage it+2 (slot last consumed at it-1).
        if (tid == 0) {
            int j = it + 2;
            if (j < NIT) {
                int sj = j % NSTAGE;
                if (j >= NSTAGE)
                    MBAR_WAIT(EMPTY0 + 8 * sj, ((j - NSTAGE) / NSTAGE) & 1);
                uint32_t st = sb + 1024 + sj * 32768;
                MBAR_EXPECT_TX(FULL0 + 8 * sj, 32768u);
                bulk_g2s(st,         srcA + (size_t)j * 1024, 16384u, FULL0 + 8 * sj);
                bulk_g2s(st + 16384, srcB + (size_t)j * 1024, 16384u, FULL0 + 8 * sj);
            }
        }

        // Consumers: wait for stage fill.
        MBAR_WAIT(FULL0 + 8 * s, (it / NSTAGE) & 1);

        const uint4* As = stage_base + s * STAGE_U4 + wmb * 128 + lane;
        const uint4* Bs = stage_base + s * STAGE_U4 + 1024 + wnb * 64 + lane;

        #pragma unroll
        for (int kp = 0; kp < 2; kp++) {          // two k32 halves of BK=64
            uint4 bv[8];
            #pragma unroll
            for (int nt = 0; nt < 8; nt++)
                bv[nt] = Bs[nt * 64 + kp * 32];
            #pragma unroll
            for (int kk = 0; kk < 2; kk++) {      // two k16 steps per k32
                uint4 av[4];
                #pragma unroll
                for (int mt = 0; mt < 4; mt++)
                    av[mt] = As[mt * 128 + (kp * 2 + kk) * 32];
                #pragma unroll
                for (int mt = 0; mt < 4; mt++)
                    #pragma unroll
                    for (int nt = 0; nt < 8; nt++) {
                        uint32_t b0 = kk ? bv[nt].z : bv[nt].x;
                        uint32_t b1 = kk ? bv[nt].w : bv[nt].y;
                        mma_f16(acc[mt][nt], av[mt], b0, b1);
                    }
            }
        }

        // Stage consumed (mma.sync converged => all lanes' LDS done).
        if (lane == 0) MBAR_ARRIVE(EMPTY0 + 8 * s);
    }

    // ---- fused LSTM gate epilogue (64-wide permute groups) ----
    const int wm   = (wid >> 1) * 64;
    const int wn   = (wid & 1) * 64;
    const int ublk = (bn + wn) >> 6;
    const int ucol = ublk * 16 + tig * 2;

    float2 bias2[8];
    #pragma unroll
    for (int nt = 0; nt < 8; nt++)
        bias2[nt] = *(const float2*)&g_bias[bn + wn + nt * 8 + tig * 2];

    #pragma unroll
    for (int mt = 0; mt < 4; mt++) {
        #pragma unroll
        for (int rs = 0; rs < 2; rs++) {
            const int row = bm + wm + mt * 16 + rs * 8 + g;
            #pragma unroll
            for (int hi = 0; hi < 2; hi++) {
                const int u = ucol + hi * 8;
                float2 cv = *(const float2*)&c_t[(size_t)row * H_DIM + u];
                float ce[2] = {cv.x, cv.y};
                float hn[2], cn[2];
                #pragma unroll
                for (int e = 0; e < 2; e++) {
                    float bi_i = e ? bias2[0 + hi].y : bias2[0 + hi].x;
                    float bi_f = e ? bias2[2 + hi].y : bias2[2 + hi].x;
                    float bi_g = e ? bias2[4 + hi].y : bias2[4 + hi].x;
                    float bi_o = e ? bias2[6 + hi].y : bias2[6 + hi].x;
                    float zi = acc[mt][0 + hi][rs * 2 + e] + bi_i;
                    float zf = acc[mt][2 + hi][rs * 2 + e] + bi_f;
                    float zg = acc[mt][4 + hi][rs * 2 + e] + bi_g;
                    float zo = acc[mt][6 + hi][rs * 2 + e] + bi_o;
                    float ig = sig_f(zi);
                    float fg = sig_f(zf);
                    float gg = tanh_f(zg);
                    float og = sig_f(zo);
                    float cnew = fg * ce[e] + ig * gg;
                    cn[e] = cnew;
                    hn[e] = og * tanh_f(cnew);
                }
                *(float2*)&out[(size_t)row * H_DIM + u] = make_float2(hn[0], hn[1]);
                *(float2*)&out[(size_t)B_DIM * H_DIM + (size_t)row * H_DIM + u] =
                    make_float2(cn[0], cn[1]);
            }
        }
    }
}

// ---------------------------------------------------------------------------
// Launch. Inputs: input, h_t, c_t, w_i, w_h, b_i, b_h
// ---------------------------------------------------------------------------
extern "C" void kernel_launch(void* const* d_in, const int* in_sizes, int n_in,
                              void* d_out, int out_size)
{
    const float* x   = (const float*)d_in[0];
    const float* h_t = (const float*)d_in[1];
    const float* c_t = (const float*)d_in[2];
    const float* w_i = (const float*)d_in[3];
    const float* w_h = (const float*)d_in[4];
    const float* b_i = (const float*)d_in[5];
    const float* b_h = (const float*)d_in[6];
    float* out = (float*)d_out;

    cudaFuncSetAttribute(lstm_gemm_mma,
                         cudaFuncAttributeMaxDynamicSharedMemorySize, SMEM_BYTES);

    prep_all<<<8208, 256>>>(x, h_t, w_i, w_h, b_i, b_h);

    lstm_gemm_mma<<<dim3(FOURH / BN, B_DIM / BM), 128, SMEM_BYTES>>>(c_t, out);
}